// round 1
// baseline (speedup 1.0000x reference)
#include <cuda_runtime.h>
#include <math.h>
#include <stdint.h>

#define D_MODEL 1024
#define NHEAD   16
#define HDIM    64
#define FFH     2048
#define BATCH   4
#define SEQ     2048
#define NTOK    (BATCH * SEQ)   // 8192

// ---------------- scratch (alloc-free: __device__ globals) ----------------
__device__ float g_h[NTOK * D_MODEL];        // ln output          (32 MB)
__device__ float g_qkv[NTOK * 3 * D_MODEL];  // qkv projection     (96 MB)
__device__ float g_ctx[NTOK * D_MODEL];      // attention context  (32 MB)
__device__ float g_x1[NTOK * D_MODEL];       // x + attended       (32 MB)
__device__ float g_ffh[NTOK * FFH];          // gelu(ff1)          (64 MB)

// ---------------- LayerNorm: one row (1024) per block of 256 --------------
__global__ __launch_bounds__(256) void ln_kernel(const float* __restrict__ x,
                                                 const float* __restrict__ g,
                                                 const float* __restrict__ b,
                                                 float* __restrict__ out) {
    int row = blockIdx.x;
    int tid = threadIdx.x;
    const float* xr = x + (size_t)row * D_MODEL;

    float4 xv = *(const float4*)(xr + tid * 4);
    float s  = xv.x + xv.y + xv.z + xv.w;
    float ss = xv.x * xv.x + xv.y * xv.y + xv.z * xv.z + xv.w * xv.w;

    __shared__ float red0[32], red1[32];
    #pragma unroll
    for (int o = 16; o > 0; o >>= 1) {
        s  += __shfl_xor_sync(0xffffffffu, s,  o);
        ss += __shfl_xor_sync(0xffffffffu, ss, o);
    }
    int warp = tid >> 5, lane = tid & 31;
    if (lane == 0) { red0[warp] = s; red1[warp] = ss; }
    __syncthreads();
    if (warp == 0) {
        float a  = (lane < 8) ? red0[lane] : 0.f;
        float a2 = (lane < 8) ? red1[lane] : 0.f;
        #pragma unroll
        for (int o = 4; o > 0; o >>= 1) {
            a  += __shfl_xor_sync(0xffffffffu, a,  o);
            a2 += __shfl_xor_sync(0xffffffffu, a2, o);
        }
        if (lane == 0) { red0[0] = a; red1[0] = a2; }
    }
    __syncthreads();

    float mean = red0[0] * (1.0f / D_MODEL);
    float var  = red1[0] * (1.0f / D_MODEL) - mean * mean;
    float rstd = rsqrtf(var + 1e-5f);

    float4 gv = *(const float4*)(g + tid * 4);
    float4 bv = *(const float4*)(b + tid * 4);
    float4 o;
    o.x = (xv.x - mean) * rstd * gv.x + bv.x;
    o.y = (xv.y - mean) * rstd * gv.y + bv.y;
    o.z = (xv.z - mean) * rstd * gv.z + bv.z;
    o.w = (xv.w - mean) * rstd * gv.w + bv.w;
    *(float4*)(out + (size_t)row * D_MODEL + tid * 4) = o;
}

// ---------------- exact GELU ----------------
__device__ __forceinline__ float gelu_exact(float v) {
    return 0.5f * v * (1.0f + erff(v * 0.70710678118654752f));
}

// ---------------- tiled SGEMM: C = A[MxK] * B[KxN] + bias (+gelu)(+res) ----
// BM=BN=64, BK=16, blockDim(16,16), 4x4 register tile per thread.
template <bool GELU, bool RES>
__global__ __launch_bounds__(256) void gemm_kernel(const float* __restrict__ A,
                                                   const float* __restrict__ B,
                                                   const float* __restrict__ bias,
                                                   const float* __restrict__ R,
                                                   float* __restrict__ C,
                                                   int M, int N, int K) {
    __shared__ float As[16][64];   // [k][m]
    __shared__ float Bs[16][64];   // [k][n]

    int tx = threadIdx.x, ty = threadIdx.y;
    int tid = ty * 16 + tx;
    int m0 = blockIdx.y * 64, n0 = blockIdx.x * 64;

    int ar = tid >> 2;          // 0..63  (m within tile)
    int ac = (tid & 3) * 4;     // 0,4,8,12 (k within tile)
    int br = tid >> 4;          // 0..15  (k within tile)
    int bc = (tid & 15) * 4;    // 0..60  (n within tile)

    float acc[4][4];
    #pragma unroll
    for (int i = 0; i < 4; i++)
        #pragma unroll
        for (int j = 0; j < 4; j++) acc[i][j] = 0.f;

    for (int k0 = 0; k0 < K; k0 += 16) {
        float4 av = *(const float4*)(A + (size_t)(m0 + ar) * K + k0 + ac);
        As[ac + 0][ar] = av.x;
        As[ac + 1][ar] = av.y;
        As[ac + 2][ar] = av.z;
        As[ac + 3][ar] = av.w;
        *(float4*)&Bs[br][bc] = *(const float4*)(B + (size_t)(k0 + br) * N + n0 + bc);
        __syncthreads();

        #pragma unroll
        for (int k = 0; k < 16; k++) {
            float4 a = *(const float4*)&As[k][ty * 4];
            float4 b = *(const float4*)&Bs[k][tx * 4];
            float ax[4] = {a.x, a.y, a.z, a.w};
            float bx[4] = {b.x, b.y, b.z, b.w};
            #pragma unroll
            for (int i = 0; i < 4; i++)
                #pragma unroll
                for (int j = 0; j < 4; j++) acc[i][j] += ax[i] * bx[j];
        }
        __syncthreads();
    }

    float4 bv = *(const float4*)(bias + n0 + tx * 4);
    #pragma unroll
    for (int i = 0; i < 4; i++) {
        int row = m0 + ty * 4 + i;
        float4 o;
        o.x = acc[i][0] + bv.x;
        o.y = acc[i][1] + bv.y;
        o.z = acc[i][2] + bv.z;
        o.w = acc[i][3] + bv.w;
        if (GELU) {
            o.x = gelu_exact(o.x); o.y = gelu_exact(o.y);
            o.z = gelu_exact(o.z); o.w = gelu_exact(o.w);
        }
        if (RES) {
            float4 rv = *(const float4*)(R + (size_t)row * N + n0 + tx * 4);
            o.x += rv.x; o.y += rv.y; o.z += rv.z; o.w += rv.w;
        }
        *(float4*)(C + (size_t)row * N + n0 + tx * 4) = o;
    }
}

// ---------------- fused attention (flash-style, online softmax) ------------
// grid = (SEQ/128, NHEAD, BATCH), block = 128 threads, 1 thread = 1 query row.
__global__ __launch_bounds__(128) void attn_kernel(const float* __restrict__ qkv,
                                                   float* __restrict__ ctx) {
    __shared__ float Ks[64][64];
    __shared__ float Vs[64][64];

    int b = blockIdx.z, h = blockIdx.y;
    int q = blockIdx.x * 128 + threadIdx.x;
    int t = b * SEQ + q;
    const float scale = 0.125f;  // 1/sqrt(64)

    float qreg[64];
    const float* qp = qkv + (size_t)t * (3 * D_MODEL) + h * HDIM;
    #pragma unroll
    for (int d = 0; d < 64; d += 4) {
        float4 v = *(const float4*)(qp + d);
        qreg[d + 0] = v.x * scale;
        qreg[d + 1] = v.y * scale;
        qreg[d + 2] = v.z * scale;
        qreg[d + 3] = v.w * scale;
    }

    float m = -1e30f, l = 0.f;
    float acc[64];
    #pragma unroll
    for (int d = 0; d < 64; d++) acc[d] = 0.f;

    for (int kt = 0; kt < SEQ; kt += 64) {
        #pragma unroll
        for (int rep = 0; rep < 8; rep++) {
            int lin = rep * 128 + threadIdx.x;   // 0..1023 float4s
            int key = lin >> 4;
            int d4  = (lin & 15) * 4;
            size_t base = (size_t)(b * SEQ + kt + key) * (3 * D_MODEL) + h * HDIM + d4;
            *(float4*)&Ks[key][d4] = *(const float4*)(qkv + base + D_MODEL);
            *(float4*)&Vs[key][d4] = *(const float4*)(qkv + base + 2 * D_MODEL);
        }
        __syncthreads();

        for (int j = 0; j < 64; j++) {
            float s = 0.f;
            #pragma unroll
            for (int d = 0; d < 64; d += 4) {
                float4 kv = *(const float4*)&Ks[j][d];
                s += qreg[d + 0] * kv.x + qreg[d + 1] * kv.y +
                     qreg[d + 2] * kv.z + qreg[d + 3] * kv.w;
            }
            if (s > m) {
                float c = __expf(m - s);
                m = s;
                l *= c;
                #pragma unroll
                for (int d = 0; d < 64; d++) acc[d] *= c;
            }
            float p = __expf(s - m);
            l += p;
            #pragma unroll
            for (int d = 0; d < 64; d += 4) {
                float4 vv = *(const float4*)&Vs[j][d];
                acc[d + 0] += p * vv.x;
                acc[d + 1] += p * vv.y;
                acc[d + 2] += p * vv.z;
                acc[d + 3] += p * vv.w;
            }
        }
        __syncthreads();
    }

    float inv = 1.0f / l;
    float* op = ctx + (size_t)t * D_MODEL + h * HDIM;
    #pragma unroll
    for (int d = 0; d < 64; d += 4) {
        float4 o;
        o.x = acc[d + 0] * inv;
        o.y = acc[d + 1] * inv;
        o.z = acc[d + 2] * inv;
        o.w = acc[d + 3] * inv;
        *(float4*)(op + d) = o;
    }
}

// ---------------- launch ----------------
extern "C" void kernel_launch(void* const* d_in, const int* in_sizes, int n_in,
                              void* d_out, int out_size) {
    const float* x     = (const float*)d_in[0];
    const float* qkv_w = (const float*)d_in[1];
    const float* qkv_b = (const float*)d_in[2];
    const float* out_w = (const float*)d_in[3];
    const float* out_b = (const float*)d_in[4];
    const float* ff1_w = (const float*)d_in[5];
    const float* ff1_b = (const float*)d_in[6];
    const float* ff2_w = (const float*)d_in[7];
    const float* ff2_b = (const float*)d_in[8];
    const float* ln1_g = (const float*)d_in[9];
    const float* ln1_b = (const float*)d_in[10];
    const float* ln2_g = (const float*)d_in[11];
    const float* ln2_b = (const float*)d_in[12];
    float* out = (float*)d_out;

    float *h, *qkv, *ctx, *x1, *ffh;
    cudaGetSymbolAddress((void**)&h,   g_h);
    cudaGetSymbolAddress((void**)&qkv, g_qkv);
    cudaGetSymbolAddress((void**)&ctx, g_ctx);
    cudaGetSymbolAddress((void**)&x1,  g_x1);
    cudaGetSymbolAddress((void**)&ffh, g_ffh);

    dim3 tb(16, 16);

    // 1. h = LN1(x)
    ln_kernel<<<NTOK, 256>>>(x, ln1_g, ln1_b, h);
    // 2. qkv = h @ qkv_w + qkv_b
    gemm_kernel<false, false><<<dim3(3 * D_MODEL / 64, NTOK / 64), tb>>>(
        h, qkv_w, qkv_b, nullptr, qkv, NTOK, 3 * D_MODEL, D_MODEL);
    // 3. ctx = attention(qkv)
    attn_kernel<<<dim3(SEQ / 128, NHEAD, BATCH), 128>>>(qkv, ctx);
    // 4. x1 = ctx @ out_w + out_b + x
    gemm_kernel<false, true><<<dim3(D_MODEL / 64, NTOK / 64), tb>>>(
        ctx, out_w, out_b, x, x1, NTOK, D_MODEL, D_MODEL);
    // 5. h = LN2(x1)
    ln_kernel<<<NTOK, 256>>>(x1, ln2_g, ln2_b, h);
    // 6. ffh = gelu(h @ ff1_w + ff1_b)
    gemm_kernel<true, false><<<dim3(FFH / 64, NTOK / 64), tb>>>(
        h, ff1_w, ff1_b, nullptr, ffh, NTOK, FFH, D_MODEL);
    // 7. out = ffh @ ff2_w + ff2_b + x1
    gemm_kernel<false, true><<<dim3(D_MODEL / 64, NTOK / 64), tb>>>(
        ffh, ff2_w, ff2_b, x1, out, NTOK, D_MODEL, FFH);
}

// round 3
// speedup vs baseline: 1.4282x; 1.4282x over previous
#include <cuda_runtime.h>
#include <cuda_bf16.h>
#include <math.h>
#include <stdint.h>

#define D_MODEL 1024
#define NHEAD   16
#define HDIM    64
#define FFH     2048
#define BATCH   4
#define SEQ     2048
#define NTOK    (BATCH * SEQ)   // 8192

// ---------------- scratch (alloc-free: __device__ globals) ----------------
__device__ float g_h[NTOK * D_MODEL];
__device__ float g_qkv[NTOK * 3 * D_MODEL];
__device__ float g_ctx[NTOK * D_MODEL];
__device__ float g_x1[NTOK * D_MODEL];
__device__ float g_ffh[NTOK * FFH];

// ======================= helpers =======================
__device__ __forceinline__ uint32_t smem_u32(const void* p) {
    uint32_t a;
    asm("{ .reg .u64 t; cvta.to.shared.u64 t, %1; cvt.u32.u64 %0, t; }" : "=r"(a) : "l"(p));
    return a;
}
__device__ __forceinline__ void ldmx4(uint32_t& r0, uint32_t& r1, uint32_t& r2, uint32_t& r3,
                                      uint32_t addr) {
    asm volatile("ldmatrix.sync.aligned.m8n8.x4.shared.b16 {%0,%1,%2,%3}, [%4];"
                 : "=r"(r0), "=r"(r1), "=r"(r2), "=r"(r3) : "r"(addr));
}
__device__ __forceinline__ void ldmx2(uint32_t& r0, uint32_t& r1, uint32_t addr) {
    asm volatile("ldmatrix.sync.aligned.m8n8.x2.shared.b16 {%0,%1}, [%2];"
                 : "=r"(r0), "=r"(r1) : "r"(addr));
}
__device__ __forceinline__ void mma_bf16(float* d, const uint32_t* a, const uint32_t* b) {
    asm volatile(
        "mma.sync.aligned.m16n8k16.row.col.f32.bf16.bf16.f32 "
        "{%0,%1,%2,%3},{%4,%5,%6,%7},{%8,%9},{%0,%1,%2,%3};"
        : "+f"(d[0]), "+f"(d[1]), "+f"(d[2]), "+f"(d[3])
        : "r"(a[0]), "r"(a[1]), "r"(a[2]), "r"(a[3]), "r"(b[0]), "r"(b[1]));
}
__device__ __forceinline__ void split2(float a, float b, uint32_t& hi, uint32_t& lo) {
    __nv_bfloat16 ah = __float2bfloat16_rn(a), bh = __float2bfloat16_rn(b);
    float ar = a - __bfloat162float(ah);
    float br = b - __bfloat162float(bh);
    __nv_bfloat162 h = __halves2bfloat162(ah, bh);
    __nv_bfloat162 l = __halves2bfloat162(__float2bfloat16_rn(ar), __float2bfloat16_rn(br));
    hi = *reinterpret_cast<uint32_t*>(&h);
    lo = *reinterpret_cast<uint32_t*>(&l);
}
__device__ __forceinline__ float gelu_exact(float v) {
    return 0.5f * v * (1.0f + erff(v * 0.70710678118654752f));
}

// ======================= HMMA bf16-split GEMM =======================
// C[M,N] = A[M,K] @ W[K,N] + bias (+gelu)(+residual), fp32 in/out.
// CTA 128x128, BK=32, 512 threads, warp grid 4x4, warp tile 32x32.
// SMEM tiles: bf16, row pitch 80 B (conflict-free ldmatrix), double buffered.
#define TPITCH 80
#define TILE_B (128 * TPITCH)          // 10240 per tile
#define BUF_B  (4 * TILE_B)            // AsH, AsL, BsH, BsL
#define GEMM_SMEM (2 * BUF_B)          // 81920

template <bool GELU, bool RES>
__global__ __launch_bounds__(512, 1) void hmma_gemm(const float* __restrict__ A,
                                                    const float* __restrict__ W,
                                                    const float* __restrict__ bias,
                                                    const float* __restrict__ R,
                                                    float* __restrict__ C,
                                                    int M, int N, int K) {
    extern __shared__ char smem[];
    const uint32_t sb = smem_u32(smem);
    const int tid = threadIdx.x;
    const int lane = tid & 31;
    const int wid = tid >> 5;
    const int wm = wid & 3;          // m slice (32 rows)
    const int wn = wid >> 2;         // n slice (32 cols)
    const int m0 = blockIdx.y * 128, n0 = blockIdx.x * 128;

    float acc[2][4][4];
    #pragma unroll
    for (int i = 0; i < 2; i++)
        #pragma unroll
        for (int j = 0; j < 4; j++)
            #pragma unroll
            for (int l = 0; l < 4; l++) acc[i][j][l] = 0.f;

    const int nch = K >> 5;

    // staging lambda: chunk c into buffer buf
    auto stage = [&](int c, int buf) {
        const int k0 = c << 5;
        char* base = smem + buf * BUF_B;
        #pragma unroll
        for (int rep = 0; rep < 2; rep++) {
            int idx = rep * 512 + tid;          // 0..1023
            {   // A: row = idx/8, k = (idx%8)*4
                int row = idx >> 3;
                int k = (idx & 7) * 4;
                float4 v = *(const float4*)(A + (size_t)(m0 + row) * K + k0 + k);
                uint32_t h01, l01, h23, l23;
                split2(v.x, v.y, h01, l01);
                split2(v.z, v.w, h23, l23);
                uint32_t off = row * TPITCH + k * 2;
                *(uint2*)(base + off) = make_uint2(h01, h23);             // AsH
                *(uint2*)(base + TILE_B + off) = make_uint2(l01, l23);    // AsL
            }
            {   // B: n = idx%128, k4 = idx/128  (Bs[n][k] = W[k][n])
                int n = idx & 127;
                int k4 = idx >> 7;
                const float* wp = W + (size_t)(k0 + k4 * 4) * N + n0 + n;
                float v0 = wp[0];
                float v1 = wp[(size_t)N];
                float v2 = wp[2 * (size_t)N];
                float v3 = wp[3 * (size_t)N];
                uint32_t h01, l01, h23, l23;
                split2(v0, v1, h01, l01);
                split2(v2, v3, h23, l23);
                uint32_t off = n * TPITCH + k4 * 8;
                *(uint2*)(base + 2 * TILE_B + off) = make_uint2(h01, h23);  // BsH
                *(uint2*)(base + 3 * TILE_B + off) = make_uint2(l01, l23);  // BsL
            }
        }
    };

    stage(0, 0);
    __syncthreads();

    for (int c = 0; c < nch; c++) {
        int buf = c & 1;
        if (c + 1 < nch) stage(c + 1, buf ^ 1);

        const uint32_t bufb = sb + buf * BUF_B;
        #pragma unroll
        for (int ks = 0; ks < 2; ks++) {
            const uint32_t kb = ks * 32;   // 16 k * 2B
            uint32_t aH[2][4], aL[2][4], bH[4][2], bL[4][2];
            #pragma unroll
            for (int mt = 0; mt < 2; mt++) {
                uint32_t ar = (uint32_t)((wm * 32 + mt * 16 + (lane & 15)) * TPITCH)
                            + kb + ((lane >> 4) << 4);
                ldmx4(aH[mt][0], aH[mt][1], aH[mt][2], aH[mt][3], bufb + ar);
                ldmx4(aL[mt][0], aL[mt][1], aL[mt][2], aL[mt][3], bufb + TILE_B + ar);
            }
            #pragma unroll
            for (int nt = 0; nt < 4; nt++) {
                uint32_t br = (uint32_t)((wn * 32 + nt * 8 + (lane & 7)) * TPITCH)
                            + kb + (((lane >> 3) & 1) << 4);
                ldmx2(bH[nt][0], bH[nt][1], bufb + 2 * TILE_B + br);
                ldmx2(bL[nt][0], bL[nt][1], bufb + 3 * TILE_B + br);
            }
            #pragma unroll
            for (int mt = 0; mt < 2; mt++)
                #pragma unroll
                for (int nt = 0; nt < 4; nt++) {
                    mma_bf16(acc[mt][nt], aH[mt], bH[nt]);
                    mma_bf16(acc[mt][nt], aL[mt], bH[nt]);
                    mma_bf16(acc[mt][nt], aH[mt], bL[nt]);
                }
        }
        __syncthreads();
    }

    // ---- epilogue ----
    #pragma unroll
    for (int mt = 0; mt < 2; mt++) {
        #pragma unroll
        for (int nt = 0; nt < 4; nt++) {
            int col = n0 + wn * 32 + nt * 8 + (lane & 3) * 2;
            float b0 = bias[col], b1 = bias[col + 1];
            #pragma unroll
            for (int half = 0; half < 2; half++) {
                int row = m0 + wm * 32 + mt * 16 + (lane >> 2) + half * 8;
                float o0 = acc[mt][nt][half * 2 + 0] + b0;
                float o1 = acc[mt][nt][half * 2 + 1] + b1;
                if (GELU) { o0 = gelu_exact(o0); o1 = gelu_exact(o1); }
                if (RES) {
                    const float* rp = R + (size_t)row * N + col;
                    o0 += rp[0]; o1 += rp[1];
                }
                *(float2*)(C + (size_t)row * N + col) = make_float2(o0, o1);
            }
        }
    }
}

// ---------------- LayerNorm ----------------
__global__ __launch_bounds__(256) void ln_kernel(const float* __restrict__ x,
                                                 const float* __restrict__ g,
                                                 const float* __restrict__ b,
                                                 float* __restrict__ out) {
    int row = blockIdx.x;
    int tid = threadIdx.x;
    const float* xr = x + (size_t)row * D_MODEL;

    float4 xv = *(const float4*)(xr + tid * 4);
    float s  = xv.x + xv.y + xv.z + xv.w;
    float ss = xv.x * xv.x + xv.y * xv.y + xv.z * xv.z + xv.w * xv.w;

    __shared__ float red0[32], red1[32];
    #pragma unroll
    for (int o = 16; o > 0; o >>= 1) {
        s  += __shfl_xor_sync(0xffffffffu, s,  o);
        ss += __shfl_xor_sync(0xffffffffu, ss, o);
    }
    int warp = tid >> 5, lane = tid & 31;
    if (lane == 0) { red0[warp] = s; red1[warp] = ss; }
    __syncthreads();
    if (warp == 0) {
        float a  = (lane < 8) ? red0[lane] : 0.f;
        float a2 = (lane < 8) ? red1[lane] : 0.f;
        #pragma unroll
        for (int o = 4; o > 0; o >>= 1) {
            a  += __shfl_xor_sync(0xffffffffu, a,  o);
            a2 += __shfl_xor_sync(0xffffffffu, a2, o);
        }
        if (lane == 0) { red0[0] = a; red1[0] = a2; }
    }
    __syncthreads();

    float mean = red0[0] * (1.0f / D_MODEL);
    float var  = red1[0] * (1.0f / D_MODEL) - mean * mean;
    float rstd = rsqrtf(var + 1e-5f);

    float4 gv = *(const float4*)(g + tid * 4);
    float4 bv = *(const float4*)(b + tid * 4);
    float4 o;
    o.x = (xv.x - mean) * rstd * gv.x + bv.x;
    o.y = (xv.y - mean) * rstd * gv.y + bv.y;
    o.z = (xv.z - mean) * rstd * gv.z + bv.z;
    o.w = (xv.w - mean) * rstd * gv.w + bv.w;
    *(float4*)(out + (size_t)row * D_MODEL + tid * 4) = o;
}

// ---------------- fused attention (flash-style, online softmax) ------------
__global__ __launch_bounds__(128) void attn_kernel(const float* __restrict__ qkv,
                                                   float* __restrict__ ctx) {
    __shared__ float Ks[64][64];
    __shared__ float Vs[64][64];

    int b = blockIdx.z, h = blockIdx.y;
    int q = blockIdx.x * 128 + threadIdx.x;
    int t = b * SEQ + q;
    const float scale = 0.125f;

    float qreg[64];
    const float* qp = qkv + (size_t)t * (3 * D_MODEL) + h * HDIM;
    #pragma unroll
    for (int d = 0; d < 64; d += 4) {
        float4 v = *(const float4*)(qp + d);
        qreg[d + 0] = v.x * scale;
        qreg[d + 1] = v.y * scale;
        qreg[d + 2] = v.z * scale;
        qreg[d + 3] = v.w * scale;
    }

    float m = -1e30f, l = 0.f;
    float acc[64];
    #pragma unroll
    for (int d = 0; d < 64; d++) acc[d] = 0.f;

    for (int kt = 0; kt < SEQ; kt += 64) {
        #pragma unroll
        for (int rep = 0; rep < 8; rep++) {
            int lin = rep * 128 + threadIdx.x;
            int key = lin >> 4;
            int d4  = (lin & 15) * 4;
            size_t base = (size_t)(b * SEQ + kt + key) * (3 * D_MODEL) + h * HDIM + d4;
            *(float4*)&Ks[key][d4] = *(const float4*)(qkv + base + D_MODEL);
            *(float4*)&Vs[key][d4] = *(const float4*)(qkv + base + 2 * D_MODEL);
        }
        __syncthreads();

        for (int j = 0; j < 64; j++) {
            float s = 0.f;
            #pragma unroll
            for (int d = 0; d < 64; d += 4) {
                float4 kv = *(const float4*)&Ks[j][d];
                s += qreg[d + 0] * kv.x + qreg[d + 1] * kv.y +
                     qreg[d + 2] * kv.z + qreg[d + 3] * kv.w;
            }
            if (s > m) {
                float c = __expf(m - s);
                m = s;
                l *= c;
                #pragma unroll
                for (int d = 0; d < 64; d++) acc[d] *= c;
            }
            float p = __expf(s - m);
            l += p;
            #pragma unroll
            for (int d = 0; d < 64; d += 4) {
                float4 vv = *(const float4*)&Vs[j][d];
                acc[d + 0] += p * vv.x;
                acc[d + 1] += p * vv.y;
                acc[d + 2] += p * vv.z;
                acc[d + 3] += p * vv.w;
            }
        }
        __syncthreads();
    }

    float inv = 1.0f / l;
    float* op = ctx + (size_t)t * D_MODEL + h * HDIM;
    #pragma unroll
    for (int d = 0; d < 64; d += 4) {
        float4 o;
        o.x = acc[d + 0] * inv;
        o.y = acc[d + 1] * inv;
        o.z = acc[d + 2] * inv;
        o.w = acc[d + 3] * inv;
        *(float4*)(op + d) = o;
    }
}

// ---------------- launch ----------------
extern "C" void kernel_launch(void* const* d_in, const int* in_sizes, int n_in,
                              void* d_out, int out_size) {
    const float* x     = (const float*)d_in[0];
    const float* qkv_w = (const float*)d_in[1];
    const float* qkv_b = (const float*)d_in[2];
    const float* out_w = (const float*)d_in[3];
    const float* out_b = (const float*)d_in[4];
    const float* ff1_w = (const float*)d_in[5];
    const float* ff1_b = (const float*)d_in[6];
    const float* ff2_w = (const float*)d_in[7];
    const float* ff2_b = (const float*)d_in[8];
    const float* ln1_g = (const float*)d_in[9];
    const float* ln1_b = (const float*)d_in[10];
    const float* ln2_g = (const float*)d_in[11];
    const float* ln2_b = (const float*)d_in[12];
    float* out = (float*)d_out;

    float *h, *qkv, *ctx, *x1, *ffh;
    cudaGetSymbolAddress((void**)&h,   g_h);
    cudaGetSymbolAddress((void**)&qkv, g_qkv);
    cudaGetSymbolAddress((void**)&ctx, g_ctx);
    cudaGetSymbolAddress((void**)&x1,  g_x1);
    cudaGetSymbolAddress((void**)&ffh, g_ffh);

    cudaFuncSetAttribute(hmma_gemm<false, false>,
                         cudaFuncAttributeMaxDynamicSharedMemorySize, GEMM_SMEM);
    cudaFuncSetAttribute(hmma_gemm<false, true>,
                         cudaFuncAttributeMaxDynamicSharedMemorySize, GEMM_SMEM);
    cudaFuncSetAttribute(hmma_gemm<true, false>,
                         cudaFuncAttributeMaxDynamicSharedMemorySize, GEMM_SMEM);

    // 1. h = LN1(x)
    ln_kernel<<<NTOK, 256>>>(x, ln1_g, ln1_b, h);
    // 2. qkv = h @ qkv_w + qkv_b
    hmma_gemm<false, false><<<dim3(3 * D_MODEL / 128, NTOK / 128), 512, GEMM_SMEM>>>(
        h, qkv_w, qkv_b, nullptr, qkv, NTOK, 3 * D_MODEL, D_MODEL);
    // 3. ctx = attention(qkv)
    attn_kernel<<<dim3(SEQ / 128, NHEAD, BATCH), 128>>>(qkv, ctx);
    // 4. x1 = ctx @ out_w + out_b + x
    hmma_gemm<false, true><<<dim3(D_MODEL / 128, NTOK / 128), 512, GEMM_SMEM>>>(
        ctx, out_w, out_b, x, x1, NTOK, D_MODEL, D_MODEL);
    // 5. h = LN2(x1)
    ln_kernel<<<NTOK, 256>>>(x1, ln2_g, ln2_b, h);
    // 6. ffh = gelu(h @ ff1_w + ff1_b)
    hmma_gemm<true, false><<<dim3(FFH / 128, NTOK / 128), 512, GEMM_SMEM>>>(
        h, ff1_w, ff1_b, nullptr, ffh, NTOK, FFH, D_MODEL);
    // 7. out = ffh @ ff2_w + ff2_b + x1
    hmma_gemm<false, true><<<dim3(D_MODEL / 128, NTOK / 128), 512, GEMM_SMEM>>>(
        ffh, ff2_w, ff2_b, x1, out, NTOK, D_MODEL, FFH);
}

// round 4
// speedup vs baseline: 2.4618x; 1.7236x over previous
#include <cuda_runtime.h>
#include <cuda_bf16.h>
#include <math.h>
#include <stdint.h>

#define D_MODEL 1024
#define NHEAD   16
#define HDIM    64
#define FFH     2048
#define BATCH   4
#define SEQ     2048
#define NTOK    (BATCH * SEQ)   // 8192

// ---------------- scratch (alloc-free: __device__ globals) ----------------
__device__ float g_h[NTOK * D_MODEL];
__device__ float g_qkv[NTOK * 3 * D_MODEL];
__device__ float g_ctx[NTOK * D_MODEL];
__device__ float g_x1[NTOK * D_MODEL];
__device__ float g_ffh[NTOK * FFH];

// ======================= helpers =======================
__device__ __forceinline__ uint32_t smem_u32(const void* p) {
    uint32_t a;
    asm("{ .reg .u64 t; cvta.to.shared.u64 t, %1; cvt.u32.u64 %0, t; }" : "=r"(a) : "l"(p));
    return a;
}
__device__ __forceinline__ void ldmx4(uint32_t& r0, uint32_t& r1, uint32_t& r2, uint32_t& r3,
                                      uint32_t addr) {
    asm volatile("ldmatrix.sync.aligned.m8n8.x4.shared.b16 {%0,%1,%2,%3}, [%4];"
                 : "=r"(r0), "=r"(r1), "=r"(r2), "=r"(r3) : "r"(addr));
}
__device__ __forceinline__ void ldmx2(uint32_t& r0, uint32_t& r1, uint32_t addr) {
    asm volatile("ldmatrix.sync.aligned.m8n8.x2.shared.b16 {%0,%1}, [%2];"
                 : "=r"(r0), "=r"(r1) : "r"(addr));
}
__device__ __forceinline__ void mma_bf16(float* d, const uint32_t* a, const uint32_t* b) {
    asm volatile(
        "mma.sync.aligned.m16n8k16.row.col.f32.bf16.bf16.f32 "
        "{%0,%1,%2,%3},{%4,%5,%6,%7},{%8,%9},{%0,%1,%2,%3};"
        : "+f"(d[0]), "+f"(d[1]), "+f"(d[2]), "+f"(d[3])
        : "r"(a[0]), "r"(a[1]), "r"(a[2]), "r"(a[3]), "r"(b[0]), "r"(b[1]));
}
__device__ __forceinline__ void split2(float a, float b, uint32_t& hi, uint32_t& lo) {
    __nv_bfloat16 ah = __float2bfloat16_rn(a), bh = __float2bfloat16_rn(b);
    float ar = a - __bfloat162float(ah);
    float br = b - __bfloat162float(bh);
    __nv_bfloat162 h = __halves2bfloat162(ah, bh);
    __nv_bfloat162 l = __halves2bfloat162(__float2bfloat16_rn(ar), __float2bfloat16_rn(br));
    hi = *reinterpret_cast<uint32_t*>(&h);
    lo = *reinterpret_cast<uint32_t*>(&l);
}
__device__ __forceinline__ float gelu_exact(float v) {
    return 0.5f * v * (1.0f + erff(v * 0.70710678118654752f));
}

// ======================= HMMA bf16-split GEMM (unchanged from R3) ==========
#define TPITCH 80
#define TILE_B (128 * TPITCH)
#define BUF_B  (4 * TILE_B)
#define GEMM_SMEM (2 * BUF_B)

template <bool GELU, bool RES>
__global__ __launch_bounds__(512, 1) void hmma_gemm(const float* __restrict__ A,
                                                    const float* __restrict__ W,
                                                    const float* __restrict__ bias,
                                                    const float* __restrict__ R,
                                                    float* __restrict__ C,
                                                    int M, int N, int K) {
    extern __shared__ char smem[];
    const uint32_t sb = smem_u32(smem);
    const int tid = threadIdx.x;
    const int lane = tid & 31;
    const int wid = tid >> 5;
    const int wm = wid & 3;
    const int wn = wid >> 2;
    const int m0 = blockIdx.y * 128, n0 = blockIdx.x * 128;

    float acc[2][4][4];
    #pragma unroll
    for (int i = 0; i < 2; i++)
        #pragma unroll
        for (int j = 0; j < 4; j++)
            #pragma unroll
            for (int l = 0; l < 4; l++) acc[i][j][l] = 0.f;

    const int nch = K >> 5;

    auto stage = [&](int c, int buf) {
        const int k0 = c << 5;
        char* base = smem + buf * BUF_B;
        #pragma unroll
        for (int rep = 0; rep < 2; rep++) {
            int idx = rep * 512 + tid;
            {
                int row = idx >> 3;
                int k = (idx & 7) * 4;
                float4 v = *(const float4*)(A + (size_t)(m0 + row) * K + k0 + k);
                uint32_t h01, l01, h23, l23;
                split2(v.x, v.y, h01, l01);
                split2(v.z, v.w, h23, l23);
                uint32_t off = row * TPITCH + k * 2;
                *(uint2*)(base + off) = make_uint2(h01, h23);
                *(uint2*)(base + TILE_B + off) = make_uint2(l01, l23);
            }
            {
                int n = idx & 127;
                int k4 = idx >> 7;
                const float* wp = W + (size_t)(k0 + k4 * 4) * N + n0 + n;
                float v0 = wp[0];
                float v1 = wp[(size_t)N];
                float v2 = wp[2 * (size_t)N];
                float v3 = wp[3 * (size_t)N];
                uint32_t h01, l01, h23, l23;
                split2(v0, v1, h01, l01);
                split2(v2, v3, h23, l23);
                uint32_t off = n * TPITCH + k4 * 8;
                *(uint2*)(base + 2 * TILE_B + off) = make_uint2(h01, h23);
                *(uint2*)(base + 3 * TILE_B + off) = make_uint2(l01, l23);
            }
        }
    };

    stage(0, 0);
    __syncthreads();

    for (int c = 0; c < nch; c++) {
        int buf = c & 1;
        if (c + 1 < nch) stage(c + 1, buf ^ 1);

        const uint32_t bufb = sb + buf * BUF_B;
        #pragma unroll
        for (int ks = 0; ks < 2; ks++) {
            const uint32_t kb = ks * 32;
            uint32_t aH[2][4], aL[2][4], bH[4][2], bL[4][2];
            #pragma unroll
            for (int mt = 0; mt < 2; mt++) {
                uint32_t ar = (uint32_t)((wm * 32 + mt * 16 + (lane & 15)) * TPITCH)
                            + kb + ((lane >> 4) << 4);
                ldmx4(aH[mt][0], aH[mt][1], aH[mt][2], aH[mt][3], bufb + ar);
                ldmx4(aL[mt][0], aL[mt][1], aL[mt][2], aL[mt][3], bufb + TILE_B + ar);
            }
            #pragma unroll
            for (int nt = 0; nt < 4; nt++) {
                uint32_t br = (uint32_t)((wn * 32 + nt * 8 + (lane & 7)) * TPITCH)
                            + kb + (((lane >> 3) & 1) << 4);
                ldmx2(bH[nt][0], bH[nt][1], bufb + 2 * TILE_B + br);
                ldmx2(bL[nt][0], bL[nt][1], bufb + 3 * TILE_B + br);
            }
            #pragma unroll
            for (int mt = 0; mt < 2; mt++)
                #pragma unroll
                for (int nt = 0; nt < 4; nt++) {
                    mma_bf16(acc[mt][nt], aH[mt], bH[nt]);
                    mma_bf16(acc[mt][nt], aL[mt], bH[nt]);
                    mma_bf16(acc[mt][nt], aH[mt], bL[nt]);
                }
        }
        __syncthreads();
    }

    #pragma unroll
    for (int mt = 0; mt < 2; mt++) {
        #pragma unroll
        for (int nt = 0; nt < 4; nt++) {
            int col = n0 + wn * 32 + nt * 8 + (lane & 3) * 2;
            float b0 = bias[col], b1 = bias[col + 1];
            #pragma unroll
            for (int half = 0; half < 2; half++) {
                int row = m0 + wm * 32 + mt * 16 + (lane >> 2) + half * 8;
                float o0 = acc[mt][nt][half * 2 + 0] + b0;
                float o1 = acc[mt][nt][half * 2 + 1] + b1;
                if (GELU) { o0 = gelu_exact(o0); o1 = gelu_exact(o1); }
                if (RES) {
                    const float* rp = R + (size_t)row * N + col;
                    o0 += rp[0]; o1 += rp[1];
                }
                *(float2*)(C + (size_t)row * N + col) = make_float2(o0, o1);
            }
        }
    }
}

// ======================= HMMA flash attention =======================
// CTA: 128 q rows of one (batch, head). 8 warps, warp tile m16.
// KV tiles of 64 keys, bf16 hi/lo in smem, pitch 144.
#define AP 144
#define AQH 0
#define AQL 18432
#define AKH 36864
#define AKL 46080
#define AVH 55296
#define AVL 64512
#define ATT_SMEM 73728

__global__ __launch_bounds__(256, 2) void attn_hmma(const float* __restrict__ qkv,
                                                    float* __restrict__ ctx) {
    extern __shared__ char sm[];
    const uint32_t sb = smem_u32(sm);
    const int tid = threadIdx.x;
    const int lane = tid & 31;
    const int wid = tid >> 5;
    const int b = blockIdx.z, h = blockIdx.y;
    const int q0 = blockIdx.x * 128;

    // ---- stage Q [128][64], scaled by 1/8, split hi/lo ----
    {
        const size_t qbase = ((size_t)(b * SEQ + q0)) * (3 * D_MODEL) + h * HDIM;
        #pragma unroll
        for (int rep = 0; rep < 4; rep++) {
            int idx = rep * 256 + tid;          // 0..1023
            int row = idx >> 3;                 // 0..127
            int d4 = (idx & 7) * 8;             // 0,8,...,56
            float4 v0 = *(const float4*)(qkv + qbase + (size_t)row * (3 * D_MODEL) + d4);
            float4 v1 = *(const float4*)(qkv + qbase + (size_t)row * (3 * D_MODEL) + d4 + 4);
            uint32_t h01, l01, h23, l23, h45, l45, h67, l67;
            split2(v0.x * 0.125f, v0.y * 0.125f, h01, l01);
            split2(v0.z * 0.125f, v0.w * 0.125f, h23, l23);
            split2(v1.x * 0.125f, v1.y * 0.125f, h45, l45);
            split2(v1.z * 0.125f, v1.w * 0.125f, h67, l67);
            uint32_t off = row * AP + d4 * 2;
            *(uint4*)(sm + AQH + off) = make_uint4(h01, h23, h45, h67);
            *(uint4*)(sm + AQL + off) = make_uint4(l01, l23, l45, l67);
        }
    }

    float acc[8][4];
    #pragma unroll
    for (int i = 0; i < 8; i++)
        #pragma unroll
        for (int j = 0; j < 4; j++) acc[i][j] = 0.f;
    float mrow0 = -1e30f, mrow1 = -1e30f;
    float lrow0 = 0.f, lrow1 = 0.f;

    for (int kt = 0; kt < SEQ; kt += 64) {
        __syncthreads();   // previous tile fully consumed
        // ---- stage K tile [64 key][64 d] and V transposed [64 d][64 key] ----
        {
            const size_t kbase = ((size_t)(b * SEQ + kt)) * (3 * D_MODEL) + D_MODEL + h * HDIM;
            #pragma unroll
            for (int rep = 0; rep < 4; rep++) {
                int idx = rep * 256 + tid;      // 0..1023
                int key = idx >> 4;             // 0..63
                int d4 = (idx & 15) * 4;        // 0..60
                float4 kv4 = *(const float4*)(qkv + kbase + (size_t)key * (3 * D_MODEL) + d4);
                uint32_t h01, l01, h23, l23;
                split2(kv4.x, kv4.y, h01, l01);
                split2(kv4.z, kv4.w, h23, l23);
                uint32_t off = key * AP + d4 * 2;
                *(uint2*)(sm + AKH + off) = make_uint2(h01, h23);
                *(uint2*)(sm + AKL + off) = make_uint2(l01, l23);

                float4 vv4 = *(const float4*)(qkv + kbase + D_MODEL + (size_t)key * (3 * D_MODEL) + d4);
                float vv[4] = {vv4.x, vv4.y, vv4.z, vv4.w};
                #pragma unroll
                for (int i = 0; i < 4; i++) {
                    __nv_bfloat16 vh = __float2bfloat16_rn(vv[i]);
                    __nv_bfloat16 vl = __float2bfloat16_rn(vv[i] - __bfloat162float(vh));
                    *(__nv_bfloat16*)(sm + AVH + (d4 + i) * AP + key * 2) = vh;
                    *(__nv_bfloat16*)(sm + AVL + (d4 + i) * AP + key * 2) = vl;
                }
            }
        }
        __syncthreads();

        // ---- S = Q @ K^T (bf16 split x3) ----
        float sf[8][4];
        #pragma unroll
        for (int i = 0; i < 8; i++)
            #pragma unroll
            for (int j = 0; j < 4; j++) sf[i][j] = 0.f;

        #pragma unroll
        for (int ks = 0; ks < 4; ks++) {
            uint32_t qaddr = sb + AQH + (uint32_t)((wid * 16 + (lane & 15)) * AP)
                           + ks * 32 + ((lane >> 4) << 4);
            uint32_t qh[4], ql[4];
            ldmx4(qh[0], qh[1], qh[2], qh[3], qaddr);
            ldmx4(ql[0], ql[1], ql[2], ql[3], qaddr + (AQL - AQH));
            #pragma unroll
            for (int np = 0; np < 4; np++) {
                uint32_t kaddr = sb + AKH + (uint32_t)((np * 16 + (lane & 15)) * AP)
                               + ks * 32 + ((lane >> 4) << 4);
                uint32_t kh[4], kl[4];
                ldmx4(kh[0], kh[1], kh[2], kh[3], kaddr);
                ldmx4(kl[0], kl[1], kl[2], kl[3], kaddr + (AKL - AKH));
                uint32_t bh0[2] = {kh[0], kh[2]}, bh1[2] = {kh[1], kh[3]};
                uint32_t bl0[2] = {kl[0], kl[2]}, bl1[2] = {kl[1], kl[3]};
                mma_bf16(sf[2 * np + 0], qh, bh0);
                mma_bf16(sf[2 * np + 0], ql, bh0);
                mma_bf16(sf[2 * np + 0], qh, bl0);
                mma_bf16(sf[2 * np + 1], qh, bh1);
                mma_bf16(sf[2 * np + 1], ql, bh1);
                mma_bf16(sf[2 * np + 1], qh, bl1);
            }
        }

        // ---- online softmax ----
        float tm0 = -1e30f, tm1 = -1e30f;
        #pragma unroll
        for (int nt = 0; nt < 8; nt++) {
            tm0 = fmaxf(tm0, fmaxf(sf[nt][0], sf[nt][1]));
            tm1 = fmaxf(tm1, fmaxf(sf[nt][2], sf[nt][3]));
        }
        #pragma unroll
        for (int o = 1; o < 4; o <<= 1) {
            tm0 = fmaxf(tm0, __shfl_xor_sync(0xffffffffu, tm0, o));
            tm1 = fmaxf(tm1, __shfl_xor_sync(0xffffffffu, tm1, o));
        }
        float mn0 = fmaxf(mrow0, tm0), mn1 = fmaxf(mrow1, tm1);
        float f0 = __expf(mrow0 - mn0), f1 = __expf(mrow1 - mn1);
        mrow0 = mn0; mrow1 = mn1;
        lrow0 *= f0; lrow1 *= f1;
        #pragma unroll
        for (int dt = 0; dt < 8; dt++) {
            acc[dt][0] *= f0; acc[dt][1] *= f0;
            acc[dt][2] *= f1; acc[dt][3] *= f1;
        }
        #pragma unroll
        for (int nt = 0; nt < 8; nt++) {
            sf[nt][0] = __expf(sf[nt][0] - mn0);
            sf[nt][1] = __expf(sf[nt][1] - mn0);
            sf[nt][2] = __expf(sf[nt][2] - mn1);
            sf[nt][3] = __expf(sf[nt][3] - mn1);
            lrow0 += sf[nt][0] + sf[nt][1];
            lrow1 += sf[nt][2] + sf[nt][3];
        }

        // ---- ctx += P @ V (bf16 split x3) ----
        #pragma unroll
        for (int ks = 0; ks < 4; ks++) {
            int nt0 = 2 * ks, nt1 = 2 * ks + 1;
            uint32_t ph[4], pl[4];
            split2(sf[nt0][0], sf[nt0][1], ph[0], pl[0]);
            split2(sf[nt0][2], sf[nt0][3], ph[1], pl[1]);
            split2(sf[nt1][0], sf[nt1][1], ph[2], pl[2]);
            split2(sf[nt1][2], sf[nt1][3], ph[3], pl[3]);
            #pragma unroll
            for (int dp = 0; dp < 4; dp++) {
                uint32_t vaddr = sb + AVH + (uint32_t)((dp * 16 + (lane & 15)) * AP)
                               + ks * 32 + ((lane >> 4) << 4);
                uint32_t vh[4], vl[4];
                ldmx4(vh[0], vh[1], vh[2], vh[3], vaddr);
                ldmx4(vl[0], vl[1], vl[2], vl[3], vaddr + (AVL - AVH));
                uint32_t bh0[2] = {vh[0], vh[2]}, bh1[2] = {vh[1], vh[3]};
                uint32_t bl0[2] = {vl[0], vl[2]}, bl1[2] = {vl[1], vl[3]};
                mma_bf16(acc[2 * dp + 0], ph, bh0);
                mma_bf16(acc[2 * dp + 0], pl, bh0);
                mma_bf16(acc[2 * dp + 0], ph, bl0);
                mma_bf16(acc[2 * dp + 1], ph, bh1);
                mma_bf16(acc[2 * dp + 1], pl, bh1);
                mma_bf16(acc[2 * dp + 1], ph, bl1);
            }
        }
    }

    // ---- epilogue ----
    #pragma unroll
    for (int o = 1; o < 4; o <<= 1) {
        lrow0 += __shfl_xor_sync(0xffffffffu, lrow0, o);
        lrow1 += __shfl_xor_sync(0xffffffffu, lrow1, o);
    }
    float inv0 = 1.0f / lrow0, inv1 = 1.0f / lrow1;
    size_t t0 = (size_t)(b * SEQ + q0 + wid * 16 + (lane >> 2));
    size_t t1 = t0 + 8;
    int col = h * HDIM + (lane & 3) * 2;
    #pragma unroll
    for (int dt = 0; dt < 8; dt++) {
        *(float2*)(ctx + t0 * D_MODEL + col + dt * 8) =
            make_float2(acc[dt][0] * inv0, acc[dt][1] * inv0);
        *(float2*)(ctx + t1 * D_MODEL + col + dt * 8) =
            make_float2(acc[dt][2] * inv1, acc[dt][3] * inv1);
    }
}

// ---------------- LayerNorm ----------------
__global__ __launch_bounds__(256) void ln_kernel(const float* __restrict__ x,
                                                 const float* __restrict__ g,
                                                 const float* __restrict__ b,
                                                 float* __restrict__ out) {
    int row = blockIdx.x;
    int tid = threadIdx.x;
    const float* xr = x + (size_t)row * D_MODEL;

    float4 xv = *(const float4*)(xr + tid * 4);
    float s  = xv.x + xv.y + xv.z + xv.w;
    float ss = xv.x * xv.x + xv.y * xv.y + xv.z * xv.z + xv.w * xv.w;

    __shared__ float red0[32], red1[32];
    #pragma unroll
    for (int o = 16; o > 0; o >>= 1) {
        s  += __shfl_xor_sync(0xffffffffu, s,  o);
        ss += __shfl_xor_sync(0xffffffffu, ss, o);
    }
    int warp = tid >> 5, lane = tid & 31;
    if (lane == 0) { red0[warp] = s; red1[warp] = ss; }
    __syncthreads();
    if (warp == 0) {
        float a  = (lane < 8) ? red0[lane] : 0.f;
        float a2 = (lane < 8) ? red1[lane] : 0.f;
        #pragma unroll
        for (int o = 4; o > 0; o >>= 1) {
            a  += __shfl_xor_sync(0xffffffffu, a,  o);
            a2 += __shfl_xor_sync(0xffffffffu, a2, o);
        }
        if (lane == 0) { red0[0] = a; red1[0] = a2; }
    }
    __syncthreads();

    float mean = red0[0] * (1.0f / D_MODEL);
    float var  = red1[0] * (1.0f / D_MODEL) - mean * mean;
    float rstd = rsqrtf(var + 1e-5f);

    float4 gv = *(const float4*)(g + tid * 4);
    float4 bv = *(const float4*)(b + tid * 4);
    float4 o;
    o.x = (xv.x - mean) * rstd * gv.x + bv.x;
    o.y = (xv.y - mean) * rstd * gv.y + bv.y;
    o.z = (xv.z - mean) * rstd * gv.z + bv.z;
    o.w = (xv.w - mean) * rstd * gv.w + bv.w;
    *(float4*)(out + (size_t)row * D_MODEL + tid * 4) = o;
}

// ---------------- launch ----------------
extern "C" void kernel_launch(void* const* d_in, const int* in_sizes, int n_in,
                              void* d_out, int out_size) {
    const float* x     = (const float*)d_in[0];
    const float* qkv_w = (const float*)d_in[1];
    const float* qkv_b = (const float*)d_in[2];
    const float* out_w = (const float*)d_in[3];
    const float* out_b = (const float*)d_in[4];
    const float* ff1_w = (const float*)d_in[5];
    const float* ff1_b = (const float*)d_in[6];
    const float* ff2_w = (const float*)d_in[7];
    const float* ff2_b = (const float*)d_in[8];
    const float* ln1_g = (const float*)d_in[9];
    const float* ln1_b = (const float*)d_in[10];
    const float* ln2_g = (const float*)d_in[11];
    const float* ln2_b = (const float*)d_in[12];
    float* out = (float*)d_out;

    float *h, *qkv, *ctx, *x1, *ffh;
    cudaGetSymbolAddress((void**)&h,   g_h);
    cudaGetSymbolAddress((void**)&qkv, g_qkv);
    cudaGetSymbolAddress((void**)&ctx, g_ctx);
    cudaGetSymbolAddress((void**)&x1,  g_x1);
    cudaGetSymbolAddress((void**)&ffh, g_ffh);

    cudaFuncSetAttribute(hmma_gemm<false, false>,
                         cudaFuncAttributeMaxDynamicSharedMemorySize, GEMM_SMEM);
    cudaFuncSetAttribute(hmma_gemm<false, true>,
                         cudaFuncAttributeMaxDynamicSharedMemorySize, GEMM_SMEM);
    cudaFuncSetAttribute(hmma_gemm<true, false>,
                         cudaFuncAttributeMaxDynamicSharedMemorySize, GEMM_SMEM);
    cudaFuncSetAttribute(attn_hmma,
                         cudaFuncAttributeMaxDynamicSharedMemorySize, ATT_SMEM);

    // 1. h = LN1(x)
    ln_kernel<<<NTOK, 256>>>(x, ln1_g, ln1_b, h);
    // 2. qkv = h @ qkv_w + qkv_b
    hmma_gemm<false, false><<<dim3(3 * D_MODEL / 128, NTOK / 128), 512, GEMM_SMEM>>>(
        h, qkv_w, qkv_b, nullptr, qkv, NTOK, 3 * D_MODEL, D_MODEL);
    // 3. ctx = attention(qkv)
    attn_hmma<<<dim3(SEQ / 128, NHEAD, BATCH), 256, ATT_SMEM>>>(qkv, ctx);
    // 4. x1 = ctx @ out_w + out_b + x
    hmma_gemm<false, true><<<dim3(D_MODEL / 128, NTOK / 128), 512, GEMM_SMEM>>>(
        ctx, out_w, out_b, x, x1, NTOK, D_MODEL, D_MODEL);
    // 5. h = LN2(x1)
    ln_kernel<<<NTOK, 256>>>(x1, ln2_g, ln2_b, h);
    // 6. ffh = gelu(h @ ff1_w + ff1_b)
    hmma_gemm<true, false><<<dim3(FFH / 128, NTOK / 128), 512, GEMM_SMEM>>>(
        h, ff1_w, ff1_b, nullptr, ffh, NTOK, FFH, D_MODEL);
    // 7. out = ffh @ ff2_w + ff2_b + x1
    hmma_gemm<false, true><<<dim3(D_MODEL / 128, NTOK / 128), 512, GEMM_SMEM>>>(
        ffh, ff2_w, ff2_b, x1, out, NTOK, D_MODEL, FFH);
}

// round 5
// speedup vs baseline: 2.6913x; 1.0932x over previous
#include <cuda_runtime.h>
#include <cuda_bf16.h>
#include <math.h>
#include <stdint.h>

#define D_MODEL 1024
#define NHEAD   16
#define HDIM    64
#define FFH     2048
#define BATCH   4
#define SEQ     2048
#define NTOK    (BATCH * SEQ)   // 8192

// ---------------- scratch (alloc-free: __device__ globals) ----------------
__device__ __nv_bfloat16 g_hh[NTOK * D_MODEL];
__device__ __nv_bfloat16 g_hl[NTOK * D_MODEL];
__device__ __nv_bfloat16 g_qh[NTOK * 3 * D_MODEL];
__device__ __nv_bfloat16 g_ql[NTOK * 3 * D_MODEL];
__device__ __nv_bfloat16 g_ch[NTOK * D_MODEL];
__device__ __nv_bfloat16 g_cl[NTOK * D_MODEL];
__device__ float         g_x1[NTOK * D_MODEL];
__device__ __nv_bfloat16 g_fh[NTOK * FFH];
__device__ __nv_bfloat16 g_fl[NTOK * FFH];
// pre-split transposed weights  Wt[n][k] = W[k][n]
__device__ __nv_bfloat16 g_wqh[3 * D_MODEL * D_MODEL];
__device__ __nv_bfloat16 g_wql[3 * D_MODEL * D_MODEL];
__device__ __nv_bfloat16 g_woh[D_MODEL * D_MODEL];
__device__ __nv_bfloat16 g_wol[D_MODEL * D_MODEL];
__device__ __nv_bfloat16 g_w1h[FFH * D_MODEL];
__device__ __nv_bfloat16 g_w1l[FFH * D_MODEL];
__device__ __nv_bfloat16 g_w2h[D_MODEL * FFH];
__device__ __nv_bfloat16 g_w2l[D_MODEL * FFH];

// ======================= helpers =======================
__device__ __forceinline__ uint32_t smem_u32(const void* p) {
    uint32_t a;
    asm("{ .reg .u64 t; cvta.to.shared.u64 t, %1; cvt.u32.u64 %0, t; }" : "=r"(a) : "l"(p));
    return a;
}
__device__ __forceinline__ void cp16(uint32_t d, const void* s) {
    asm volatile("cp.async.cg.shared.global [%0], [%1], 16;" :: "r"(d), "l"(s));
}
__device__ __forceinline__ void cp_commit() {
    asm volatile("cp.async.commit_group;");
}
template <int N>
__device__ __forceinline__ void cp_wait() {
    asm volatile("cp.async.wait_group %0;" :: "n"(N));
}
__device__ __forceinline__ void ldmx4(uint32_t& r0, uint32_t& r1, uint32_t& r2, uint32_t& r3,
                                      uint32_t addr) {
    asm volatile("ldmatrix.sync.aligned.m8n8.x4.shared.b16 {%0,%1,%2,%3}, [%4];"
                 : "=r"(r0), "=r"(r1), "=r"(r2), "=r"(r3) : "r"(addr));
}
__device__ __forceinline__ void ldmx2(uint32_t& r0, uint32_t& r1, uint32_t addr) {
    asm volatile("ldmatrix.sync.aligned.m8n8.x2.shared.b16 {%0,%1}, [%2];"
                 : "=r"(r0), "=r"(r1) : "r"(addr));
}
__device__ __forceinline__ void mma_bf16(float* d, const uint32_t* a, const uint32_t* b) {
    asm volatile(
        "mma.sync.aligned.m16n8k16.row.col.f32.bf16.bf16.f32 "
        "{%0,%1,%2,%3},{%4,%5,%6,%7},{%8,%9},{%0,%1,%2,%3};"
        : "+f"(d[0]), "+f"(d[1]), "+f"(d[2]), "+f"(d[3])
        : "r"(a[0]), "r"(a[1]), "r"(a[2]), "r"(a[3]), "r"(b[0]), "r"(b[1]));
}
__device__ __forceinline__ void split2(float a, float b, uint32_t& hi, uint32_t& lo) {
    __nv_bfloat16 ah = __float2bfloat16_rn(a), bh = __float2bfloat16_rn(b);
    float ar = a - __bfloat162float(ah);
    float br = b - __bfloat162float(bh);
    __nv_bfloat162 h = __halves2bfloat162(ah, bh);
    __nv_bfloat162 l = __halves2bfloat162(__float2bfloat16_rn(ar), __float2bfloat16_rn(br));
    hi = *reinterpret_cast<uint32_t*>(&h);
    lo = *reinterpret_cast<uint32_t*>(&l);
}
__device__ __forceinline__ float gelu_exact(float v) {
    return 0.5f * v * (1.0f + erff(v * 0.70710678118654752f));
}

// ======================= weight transpose + split =======================
// W[K][N] fp32 -> Wh/Wl[N][K] bf16
__global__ __launch_bounds__(256) void wconv(const float* __restrict__ W,
                                             __nv_bfloat16* __restrict__ Wh,
                                             __nv_bfloat16* __restrict__ Wl,
                                             int N, int K) {
    __shared__ float t[32][33];
    int n0 = blockIdx.x * 32, k0 = blockIdx.y * 32;
    int tx = threadIdx.x & 31, ty = threadIdx.x >> 5;   // 32 x 8
    #pragma unroll
    for (int i = ty; i < 32; i += 8)
        t[i][tx] = W[(size_t)(k0 + i) * N + n0 + tx];
    __syncthreads();
    #pragma unroll
    for (int i = ty; i < 32; i += 8) {
        float v = t[tx][i];
        __nv_bfloat16 h = __float2bfloat16_rn(v);
        __nv_bfloat16 l = __float2bfloat16_rn(v - __bfloat162float(h));
        size_t o = (size_t)(n0 + i) * K + k0 + tx;
        Wh[o] = h; Wl[o] = l;
    }
}

// ======================= HMMA bf16-split GEMM (pre-split inputs) ==========
// C = A @ Wt^T + bias (+gelu)(+res); A hi/lo [M][K], Wt hi/lo [N][K] bf16.
// CTA 128x128, BK=32, 512 thr, cp.async double-buffered.
#define TPITCH 80
#define TILE_B (128 * TPITCH)          // 10240
#define BUF_B  (4 * TILE_B)            // 40960
#define GEMM_SMEM (2 * BUF_B)          // 81920

template <bool GELU, bool RES, bool OSPLIT>
__global__ __launch_bounds__(512, 1) void hmma_gemm(const __nv_bfloat16* __restrict__ Ah,
                                                    const __nv_bfloat16* __restrict__ Al,
                                                    const __nv_bfloat16* __restrict__ Bth,
                                                    const __nv_bfloat16* __restrict__ Btl,
                                                    const float* __restrict__ bias,
                                                    const float* __restrict__ R,
                                                    float* __restrict__ C,
                                                    __nv_bfloat16* __restrict__ Oh,
                                                    __nv_bfloat16* __restrict__ Ol,
                                                    int M, int N, int K) {
    extern __shared__ char smem[];
    const uint32_t sb = smem_u32(smem);
    const int tid = threadIdx.x;
    const int lane = tid & 31;
    const int wid = tid >> 5;
    const int wm = wid & 3;
    const int wn = wid >> 2;
    const int m0 = blockIdx.y * 128, n0 = blockIdx.x * 128;

    const int srow = tid >> 2;          // 0..127
    const int sseg = tid & 3;           // 16B segment
    const uint32_t sdst = (uint32_t)(srow * TPITCH + sseg * 16);

    float acc[2][4][4];
    #pragma unroll
    for (int i = 0; i < 2; i++)
        #pragma unroll
        for (int j = 0; j < 4; j++)
            #pragma unroll
            for (int l = 0; l < 4; l++) acc[i][j][l] = 0.f;

    const int nch = K >> 5;

    auto stage = [&](int c, int buf) {
        const int k0 = (c << 5) + sseg * 8;
        uint32_t d = sb + buf * BUF_B + sdst;
        cp16(d,              Ah  + (size_t)(m0 + srow) * K + k0);
        cp16(d + TILE_B,     Al  + (size_t)(m0 + srow) * K + k0);
        cp16(d + 2 * TILE_B, Bth + (size_t)(n0 + srow) * K + k0);
        cp16(d + 3 * TILE_B, Btl + (size_t)(n0 + srow) * K + k0);
        cp_commit();
    };

    stage(0, 0);
    if (nch > 1) stage(1, 1);

    for (int c = 0; c < nch; c++) {
        if (c + 1 < nch) cp_wait<1>(); else cp_wait<0>();
        __syncthreads();

        const uint32_t bufb = sb + (c & 1) * BUF_B;
        #pragma unroll
        for (int ks = 0; ks < 2; ks++) {
            const uint32_t kb = ks * 32;
            uint32_t aH[2][4], aL[2][4], bH[4][2], bL[4][2];
            #pragma unroll
            for (int mt = 0; mt < 2; mt++) {
                uint32_t ar = (uint32_t)((wm * 32 + mt * 16 + (lane & 15)) * TPITCH)
                            + kb + ((lane >> 4) << 4);
                ldmx4(aH[mt][0], aH[mt][1], aH[mt][2], aH[mt][3], bufb + ar);
                ldmx4(aL[mt][0], aL[mt][1], aL[mt][2], aL[mt][3], bufb + TILE_B + ar);
            }
            #pragma unroll
            for (int nt = 0; nt < 4; nt++) {
                uint32_t br = (uint32_t)((wn * 32 + nt * 8 + (lane & 7)) * TPITCH)
                            + kb + (((lane >> 3) & 1) << 4);
                ldmx2(bH[nt][0], bH[nt][1], bufb + 2 * TILE_B + br);
                ldmx2(bL[nt][0], bL[nt][1], bufb + 3 * TILE_B + br);
            }
            #pragma unroll
            for (int mt = 0; mt < 2; mt++)
                #pragma unroll
                for (int nt = 0; nt < 4; nt++) {
                    mma_bf16(acc[mt][nt], aH[mt], bH[nt]);
                    mma_bf16(acc[mt][nt], aL[mt], bH[nt]);
                    mma_bf16(acc[mt][nt], aH[mt], bL[nt]);
                }
        }
        __syncthreads();
        if (c + 2 < nch) stage(c + 2, c & 1);
    }

    // ---- epilogue ----
    #pragma unroll
    for (int mt = 0; mt < 2; mt++) {
        #pragma unroll
        for (int nt = 0; nt < 4; nt++) {
            int col = n0 + wn * 32 + nt * 8 + (lane & 3) * 2;
            float b0 = bias[col], b1 = bias[col + 1];
            #pragma unroll
            for (int half = 0; half < 2; half++) {
                int row = m0 + wm * 32 + mt * 16 + (lane >> 2) + half * 8;
                float o0 = acc[mt][nt][half * 2 + 0] + b0;
                float o1 = acc[mt][nt][half * 2 + 1] + b1;
                if (GELU) { o0 = gelu_exact(o0); o1 = gelu_exact(o1); }
                if (RES) {
                    const float* rp = R + (size_t)row * N + col;
                    o0 += rp[0]; o1 += rp[1];
                }
                if (OSPLIT) {
                    uint32_t hi, lo;
                    split2(o0, o1, hi, lo);
                    *(uint32_t*)(Oh + (size_t)row * N + col) = hi;
                    *(uint32_t*)(Ol + (size_t)row * N + col) = lo;
                } else {
                    *(float2*)(C + (size_t)row * N + col) = make_float2(o0, o1);
                }
            }
        }
    }
}

// ======================= HMMA flash attention (pre-split qkv) ==============
#define AP 144
#define AQH 0
#define AQL 18432
#define AKH 36864
#define AKL 46080
#define AVH 55296
#define AVL 64512
#define ATT_SMEM 73728

__global__ __launch_bounds__(256, 2) void attn_hmma(const __nv_bfloat16* __restrict__ qh,
                                                    const __nv_bfloat16* __restrict__ ql,
                                                    __nv_bfloat16* __restrict__ ch,
                                                    __nv_bfloat16* __restrict__ cl) {
    extern __shared__ char sm[];
    const uint32_t sb = smem_u32(sm);
    const int tid = threadIdx.x;
    const int lane = tid & 31;
    const int wid = tid >> 5;
    const int b = blockIdx.z, h = blockIdx.y;
    const int q0 = blockIdx.x * 128;

    // ---- stage Q [128][64] hi/lo (pure copy) ----
    {
        const size_t qbase = ((size_t)(b * SEQ + q0)) * (3 * D_MODEL) + h * HDIM;
        #pragma unroll
        for (int rep = 0; rep < 4; rep++) {
            int idx = rep * 256 + tid;          // 0..1023 = 128 rows x 8 segs
            int row = idx >> 3;
            int seg = idx & 7;
            size_t src = qbase + (size_t)row * (3 * D_MODEL) + seg * 8;
            uint32_t dst = row * AP + seg * 16;
            *(uint4*)(sm + AQH + dst) = *(const uint4*)(qh + src);
            *(uint4*)(sm + AQL + dst) = *(const uint4*)(ql + src);
        }
    }

    float acc[8][4];
    #pragma unroll
    for (int i = 0; i < 8; i++)
        #pragma unroll
        for (int j = 0; j < 4; j++) acc[i][j] = 0.f;
    float mrow0 = -1e30f, mrow1 = -1e30f;
    float lrow0 = 0.f, lrow1 = 0.f;

    for (int kt = 0; kt < SEQ; kt += 64) {
        __syncthreads();
        // ---- stage K [64][64] hi/lo + V transposed [64 d][64 key] hi/lo ----
        {
            const size_t kbase = ((size_t)(b * SEQ + kt)) * (3 * D_MODEL) + D_MODEL + h * HDIM;
            #pragma unroll
            for (int rep = 0; rep < 2; rep++) {
                int idx = rep * 256 + tid;      // 0..511 = 64 rows x 8 segs
                int row = idx >> 3;
                int seg = idx & 7;
                size_t src = kbase + (size_t)row * (3 * D_MODEL) + seg * 8;
                uint32_t dst = row * AP + seg * 16;
                *(uint4*)(sm + AKH + dst) = *(const uint4*)(qh + src);
                *(uint4*)(sm + AKL + dst) = *(const uint4*)(ql + src);
            }
            const size_t vbase = kbase + D_MODEL;
            #pragma unroll
            for (int rep = 0; rep < 4; rep++) {
                int idx = rep * 256 + tid;      // 0..1023 = 64 keys x 16 d-groups
                int key = idx >> 4;
                int d4 = (idx & 15) * 4;
                uint2 hv = *(const uint2*)(qh + vbase + (size_t)key * (3 * D_MODEL) + d4);
                uint2 lv = *(const uint2*)(ql + vbase + (size_t)key * (3 * D_MODEL) + d4);
                const __nv_bfloat16* hp = (const __nv_bfloat16*)&hv;
                const __nv_bfloat16* lp = (const __nv_bfloat16*)&lv;
                #pragma unroll
                for (int i = 0; i < 4; i++) {
                    *(__nv_bfloat16*)(sm + AVH + (d4 + i) * AP + key * 2) = hp[i];
                    *(__nv_bfloat16*)(sm + AVL + (d4 + i) * AP + key * 2) = lp[i];
                }
            }
        }
        __syncthreads();

        // ---- S = Q @ K^T ----
        float sf[8][4];
        #pragma unroll
        for (int i = 0; i < 8; i++)
            #pragma unroll
            for (int j = 0; j < 4; j++) sf[i][j] = 0.f;

        #pragma unroll
        for (int ks = 0; ks < 4; ks++) {
            uint32_t qaddr = sb + AQH + (uint32_t)((wid * 16 + (lane & 15)) * AP)
                           + ks * 32 + ((lane >> 4) << 4);
            uint32_t qhf[4], qlf[4];
            ldmx4(qhf[0], qhf[1], qhf[2], qhf[3], qaddr);
            ldmx4(qlf[0], qlf[1], qlf[2], qlf[3], qaddr + (AQL - AQH));
            #pragma unroll
            for (int np = 0; np < 4; np++) {
                uint32_t kaddr = sb + AKH + (uint32_t)((np * 16 + (lane & 15)) * AP)
                               + ks * 32 + ((lane >> 4) << 4);
                uint32_t kh[4], kl[4];
                ldmx4(kh[0], kh[1], kh[2], kh[3], kaddr);
                ldmx4(kl[0], kl[1], kl[2], kl[3], kaddr + (AKL - AKH));
                uint32_t bh0[2] = {kh[0], kh[2]}, bh1[2] = {kh[1], kh[3]};
                uint32_t bl0[2] = {kl[0], kl[2]}, bl1[2] = {kl[1], kl[3]};
                mma_bf16(sf[2 * np + 0], qhf, bh0);
                mma_bf16(sf[2 * np + 0], qlf, bh0);
                mma_bf16(sf[2 * np + 0], qhf, bl0);
                mma_bf16(sf[2 * np + 1], qhf, bh1);
                mma_bf16(sf[2 * np + 1], qlf, bh1);
                mma_bf16(sf[2 * np + 1], qhf, bl1);
            }
        }
        #pragma unroll
        for (int nt = 0; nt < 8; nt++)
            #pragma unroll
            for (int j = 0; j < 4; j++) sf[nt][j] *= 0.125f;

        // ---- online softmax ----
        float tm0 = -1e30f, tm1 = -1e30f;
        #pragma unroll
        for (int nt = 0; nt < 8; nt++) {
            tm0 = fmaxf(tm0, fmaxf(sf[nt][0], sf[nt][1]));
            tm1 = fmaxf(tm1, fmaxf(sf[nt][2], sf[nt][3]));
        }
        #pragma unroll
        for (int o = 1; o < 4; o <<= 1) {
            tm0 = fmaxf(tm0, __shfl_xor_sync(0xffffffffu, tm0, o));
            tm1 = fmaxf(tm1, __shfl_xor_sync(0xffffffffu, tm1, o));
        }
        float mn0 = fmaxf(mrow0, tm0), mn1 = fmaxf(mrow1, tm1);
        float f0 = __expf(mrow0 - mn0), f1 = __expf(mrow1 - mn1);
        mrow0 = mn0; mrow1 = mn1;
        lrow0 *= f0; lrow1 *= f1;
        #pragma unroll
        for (int dt = 0; dt < 8; dt++) {
            acc[dt][0] *= f0; acc[dt][1] *= f0;
            acc[dt][2] *= f1; acc[dt][3] *= f1;
        }
        #pragma unroll
        for (int nt = 0; nt < 8; nt++) {
            sf[nt][0] = __expf(sf[nt][0] - mn0);
            sf[nt][1] = __expf(sf[nt][1] - mn0);
            sf[nt][2] = __expf(sf[nt][2] - mn1);
            sf[nt][3] = __expf(sf[nt][3] - mn1);
            lrow0 += sf[nt][0] + sf[nt][1];
            lrow1 += sf[nt][2] + sf[nt][3];
        }

        // ---- ctx += P @ V ----
        #pragma unroll
        for (int ks = 0; ks < 4; ks++) {
            int nt0 = 2 * ks, nt1 = 2 * ks + 1;
            uint32_t ph[4], pl[4];
            split2(sf[nt0][0], sf[nt0][1], ph[0], pl[0]);
            split2(sf[nt0][2], sf[nt0][3], ph[1], pl[1]);
            split2(sf[nt1][0], sf[nt1][1], ph[2], pl[2]);
            split2(sf[nt1][2], sf[nt1][3], ph[3], pl[3]);
            #pragma unroll
            for (int dp = 0; dp < 4; dp++) {
                uint32_t vaddr = sb + AVH + (uint32_t)((dp * 16 + (lane & 15)) * AP)
                               + ks * 32 + ((lane >> 4) << 4);
                uint32_t vh[4], vl[4];
                ldmx4(vh[0], vh[1], vh[2], vh[3], vaddr);
                ldmx4(vl[0], vl[1], vl[2], vl[3], vaddr + (AVL - AVH));
                uint32_t bh0[2] = {vh[0], vh[2]}, bh1[2] = {vh[1], vh[3]};
                uint32_t bl0[2] = {vl[0], vl[2]}, bl1[2] = {vl[1], vl[3]};
                mma_bf16(acc[2 * dp + 0], ph, bh0);
                mma_bf16(acc[2 * dp + 0], pl, bh0);
                mma_bf16(acc[2 * dp + 0], ph, bl0);
                mma_bf16(acc[2 * dp + 1], ph, bh1);
                mma_bf16(acc[2 * dp + 1], pl, bh1);
                mma_bf16(acc[2 * dp + 1], ph, bl1);
            }
        }
    }

    // ---- epilogue: write ctx hi/lo ----
    #pragma unroll
    for (int o = 1; o < 4; o <<= 1) {
        lrow0 += __shfl_xor_sync(0xffffffffu, lrow0, o);
        lrow1 += __shfl_xor_sync(0xffffffffu, lrow1, o);
    }
    float inv0 = 1.0f / lrow0, inv1 = 1.0f / lrow1;
    size_t t0 = (size_t)(b * SEQ + q0 + wid * 16 + (lane >> 2));
    size_t t1 = t0 + 8;
    int col = h * HDIM + (lane & 3) * 2;
    #pragma unroll
    for (int dt = 0; dt < 8; dt++) {
        uint32_t hi, lo;
        split2(acc[dt][0] * inv0, acc[dt][1] * inv0, hi, lo);
        *(uint32_t*)(ch + t0 * D_MODEL + col + dt * 8) = hi;
        *(uint32_t*)(cl + t0 * D_MODEL + col + dt * 8) = lo;
        split2(acc[dt][2] * inv1, acc[dt][3] * inv1, hi, lo);
        *(uint32_t*)(ch + t1 * D_MODEL + col + dt * 8) = hi;
        *(uint32_t*)(cl + t1 * D_MODEL + col + dt * 8) = lo;
    }
}

// ---------------- LayerNorm -> bf16 hi/lo ----------------
__global__ __launch_bounds__(256) void ln_kernel(const float* __restrict__ x,
                                                 const float* __restrict__ g,
                                                 const float* __restrict__ b,
                                                 __nv_bfloat16* __restrict__ oh,
                                                 __nv_bfloat16* __restrict__ ol) {
    int row = blockIdx.x;
    int tid = threadIdx.x;
    const float* xr = x + (size_t)row * D_MODEL;

    float4 xv = *(const float4*)(xr + tid * 4);
    float s  = xv.x + xv.y + xv.z + xv.w;
    float ss = xv.x * xv.x + xv.y * xv.y + xv.z * xv.z + xv.w * xv.w;

    __shared__ float red0[32], red1[32];
    #pragma unroll
    for (int o = 16; o > 0; o >>= 1) {
        s  += __shfl_xor_sync(0xffffffffu, s,  o);
        ss += __shfl_xor_sync(0xffffffffu, ss, o);
    }
    int warp = tid >> 5, lane = tid & 31;
    if (lane == 0) { red0[warp] = s; red1[warp] = ss; }
    __syncthreads();
    if (warp == 0) {
        float a  = (lane < 8) ? red0[lane] : 0.f;
        float a2 = (lane < 8) ? red1[lane] : 0.f;
        #pragma unroll
        for (int o = 4; o > 0; o >>= 1) {
            a  += __shfl_xor_sync(0xffffffffu, a,  o);
            a2 += __shfl_xor_sync(0xffffffffu, a2, o);
        }
        if (lane == 0) { red0[0] = a; red1[0] = a2; }
    }
    __syncthreads();

    float mean = red0[0] * (1.0f / D_MODEL);
    float var  = red1[0] * (1.0f / D_MODEL) - mean * mean;
    float rstd = rsqrtf(var + 1e-5f);

    float4 gv = *(const float4*)(g + tid * 4);
    float4 bv = *(const float4*)(b + tid * 4);
    float o0 = (xv.x - mean) * rstd * gv.x + bv.x;
    float o1 = (xv.y - mean) * rstd * gv.y + bv.y;
    float o2 = (xv.z - mean) * rstd * gv.z + bv.z;
    float o3 = (xv.w - mean) * rstd * gv.w + bv.w;
    uint32_t h01, l01, h23, l23;
    split2(o0, o1, h01, l01);
    split2(o2, o3, h23, l23);
    *(uint2*)(oh + (size_t)row * D_MODEL + tid * 4) = make_uint2(h01, h23);
    *(uint2*)(ol + (size_t)row * D_MODEL + tid * 4) = make_uint2(l01, l23);
}

// ---------------- launch ----------------
extern "C" void kernel_launch(void* const* d_in, const int* in_sizes, int n_in,
                              void* d_out, int out_size) {
    const float* x     = (const float*)d_in[0];
    const float* qkv_w = (const float*)d_in[1];
    const float* qkv_b = (const float*)d_in[2];
    const float* out_w = (const float*)d_in[3];
    const float* out_b = (const float*)d_in[4];
    const float* ff1_w = (const float*)d_in[5];
    const float* ff1_b = (const float*)d_in[6];
    const float* ff2_w = (const float*)d_in[7];
    const float* ff2_b = (const float*)d_in[8];
    const float* ln1_g = (const float*)d_in[9];
    const float* ln1_b = (const float*)d_in[10];
    const float* ln2_g = (const float*)d_in[11];
    const float* ln2_b = (const float*)d_in[12];
    float* out = (float*)d_out;

    __nv_bfloat16 *hh, *hl, *qh, *ql, *ch, *cl, *fh, *fl;
    __nv_bfloat16 *wqh, *wql, *woh, *wol, *w1h, *w1l, *w2h, *w2l;
    float* x1;
    cudaGetSymbolAddress((void**)&hh, g_hh);  cudaGetSymbolAddress((void**)&hl, g_hl);
    cudaGetSymbolAddress((void**)&qh, g_qh);  cudaGetSymbolAddress((void**)&ql, g_ql);
    cudaGetSymbolAddress((void**)&ch, g_ch);  cudaGetSymbolAddress((void**)&cl, g_cl);
    cudaGetSymbolAddress((void**)&fh, g_fh);  cudaGetSymbolAddress((void**)&fl, g_fl);
    cudaGetSymbolAddress((void**)&x1, g_x1);
    cudaGetSymbolAddress((void**)&wqh, g_wqh); cudaGetSymbolAddress((void**)&wql, g_wql);
    cudaGetSymbolAddress((void**)&woh, g_woh); cudaGetSymbolAddress((void**)&wol, g_wol);
    cudaGetSymbolAddress((void**)&w1h, g_w1h); cudaGetSymbolAddress((void**)&w1l, g_w1l);
    cudaGetSymbolAddress((void**)&w2h, g_w2h); cudaGetSymbolAddress((void**)&w2l, g_w2l);

    cudaFuncSetAttribute(hmma_gemm<false, false, true>,
                         cudaFuncAttributeMaxDynamicSharedMemorySize, GEMM_SMEM);
    cudaFuncSetAttribute(hmma_gemm<false, true, false>,
                         cudaFuncAttributeMaxDynamicSharedMemorySize, GEMM_SMEM);
    cudaFuncSetAttribute(hmma_gemm<true, false, true>,
                         cudaFuncAttributeMaxDynamicSharedMemorySize, GEMM_SMEM);
    cudaFuncSetAttribute(attn_hmma,
                         cudaFuncAttributeMaxDynamicSharedMemorySize, ATT_SMEM);

    // 0. weight conversion (transpose + bf16 split)
    wconv<<<dim3(3 * D_MODEL / 32, D_MODEL / 32), 256>>>(qkv_w, wqh, wql, 3 * D_MODEL, D_MODEL);
    wconv<<<dim3(D_MODEL / 32, D_MODEL / 32), 256>>>(out_w, woh, wol, D_MODEL, D_MODEL);
    wconv<<<dim3(FFH / 32, D_MODEL / 32), 256>>>(ff1_w, w1h, w1l, FFH, D_MODEL);
    wconv<<<dim3(D_MODEL / 32, FFH / 32), 256>>>(ff2_w, w2h, w2l, D_MODEL, FFH);

    // 1. h = LN1(x) -> hi/lo
    ln_kernel<<<NTOK, 256>>>(x, ln1_g, ln1_b, hh, hl);
    // 2. qkv = h @ qkv_w + qkv_b -> hi/lo
    hmma_gemm<false, false, true><<<dim3(3 * D_MODEL / 128, NTOK / 128), 512, GEMM_SMEM>>>(
        hh, hl, wqh, wql, qkv_b, nullptr, nullptr, qh, ql, NTOK, 3 * D_MODEL, D_MODEL);
    // 3. ctx = attention(qkv) -> hi/lo
    attn_hmma<<<dim3(SEQ / 128, NHEAD, BATCH), 256, ATT_SMEM>>>(qh, ql, ch, cl);
    // 4. x1 = ctx @ out_w + out_b + x   (fp32)
    hmma_gemm<false, true, false><<<dim3(D_MODEL / 128, NTOK / 128), 512, GEMM_SMEM>>>(
        ch, cl, woh, wol, out_b, x, x1, nullptr, nullptr, NTOK, D_MODEL, D_MODEL);
    // 5. h2 = LN2(x1) -> hi/lo
    ln_kernel<<<NTOK, 256>>>(x1, ln2_g, ln2_b, hh, hl);
    // 6. ffh = gelu(h2 @ ff1_w + ff1_b) -> hi/lo
    hmma_gemm<true, false, true><<<dim3(FFH / 128, NTOK / 128), 512, GEMM_SMEM>>>(
        hh, hl, w1h, w1l, ff1_b, nullptr, nullptr, fh, fl, NTOK, FFH, D_MODEL);
    // 7. out = ffh @ ff2_w + ff2_b + x1  (fp32)
    hmma_gemm<false, true, false><<<dim3(D_MODEL / 128, NTOK / 128), 512, GEMM_SMEM>>>(
        fh, fl, w2h, w2l, ff2_b, x1, out, nullptr, nullptr, NTOK, D_MODEL, FFH);
}